// round 12
// baseline (speedup 1.0000x reference)
#include <cuda_runtime.h>
#include <cuda_bf16.h>

#define R2C 0.70710678118654752f

__device__ __forceinline__ float soft05(float x) {
    return copysignf(fmaxf(fabsf(x) - 0.05f, 0.0f), x);
}

// x[8] -> o[8] = {RE0,RE1,RE2,RE3,RE4,SI1,SI2,SI3}, unnormalized.
__device__ __forceinline__ void dft8_real(const float* x, float* o) {
    float s04 = x[0] + x[4], d04 = x[0] - x[4];
    float s26 = x[2] + x[6], d26 = x[2] - x[6];
    float s15 = x[1] + x[5], d15 = x[1] - x[5];
    float s37 = x[3] + x[7], d37 = x[3] - x[7];
    float t1 = s04 + s26, t2 = s15 + s37;
    o[0] = t1 + t2; o[4] = t1 - t2; o[2] = s04 - s26;
    float u = d15 - d37, v = d15 + d37;
    o[1] = fmaf(R2C, u, d04); o[3] = fmaf(-R2C, u, d04);
    o[5] = fmaf(R2C, v, d26);
    o[6] = s15 - s37;
    o[7] = fmaf(R2C, v, -d26);
}

// o[u] = cosDFT_u(q) - sinDFT_u(w), raw/unscaled.
__device__ __forceinline__ void dft8_combine(const float* q, const float* w, float* o) {
    float s04 = q[0] + q[4], d04 = q[0] - q[4];
    float s26 = q[2] + q[6];
    float s15 = q[1] + q[5], d15 = q[1] - q[5];
    float s37 = q[3] + q[7], d37 = q[3] - q[7];
    float t1 = s04 + s26, t2 = s15 + s37;
    float RE0 = t1 + t2, RE4 = t1 - t2, RE2 = s04 - s26;
    float uq = d15 - d37;
    float RE1 = fmaf(R2C, uq, d04), RE3 = fmaf(-R2C, uq, d04);
    float d26w = w[2] - w[6];
    float vw = (w[1] - w[5]) + (w[3] - w[7]);
    float SI1 = fmaf(R2C, vw, d26w);
    float SI2 = (w[1] + w[5]) - (w[3] + w[7]);
    float SI3 = fmaf(R2C, vw, -d26w);
    o[0] = RE0;        o[4] = RE4;
    o[1] = RE1 - SI1;  o[7] = RE1 + SI1;
    o[2] = RE2 - SI2;  o[6] = RE2 + SI2;
    o[3] = RE3 - SI3;  o[5] = RE3 + SI3;
}

// o[u] = cosDFT_u(q) only (for lines with zero sine part).
__device__ __forceinline__ void dft8_cos(const float* q, float* o) {
    float s04 = q[0] + q[4], d04 = q[0] - q[4];
    float s26 = q[2] + q[6];
    float s15 = q[1] + q[5], d15 = q[1] - q[5];
    float s37 = q[3] + q[7], d37 = q[3] - q[7];
    float t1 = s04 + s26, t2 = s15 + s37;
    o[0] = t1 + t2; o[4] = t1 - t2;
    o[2] = s04 - s26; o[6] = o[2];
    float uq = d15 - d37;
    o[1] = fmaf(R2C, uq, d04); o[3] = fmaf(-R2C, uq, d04);
    o[5] = o[3]; o[7] = o[1];
}

// Dual conjugate columns: CR = cosDFT(q), SW = sinDFT(w).
// oA[u] = CR[u] - SW[u] (col tau), oB[u] = CR[u] + SW[u] (col 8-tau).
__device__ __forceinline__ void dft8_dual(const float* q, const float* w,
                                          float* oA, float* oB) {
    float s04 = q[0] + q[4], d04 = q[0] - q[4];
    float s26 = q[2] + q[6];
    float s15 = q[1] + q[5], d15 = q[1] - q[5];
    float s37 = q[3] + q[7], d37 = q[3] - q[7];
    float t1 = s04 + s26, t2 = s15 + s37;
    float CR0 = t1 + t2, CR4 = t1 - t2, CR2 = s04 - s26;
    float uq = d15 - d37;
    float CR1 = fmaf(R2C, uq, d04), CR3 = fmaf(-R2C, uq, d04);
    float d26w = w[2] - w[6];
    float vw = (w[1] - w[5]) + (w[3] - w[7]);
    float SW1 = fmaf(R2C, vw, d26w);
    float SW2 = (w[1] + w[5]) - (w[3] + w[7]);
    float SW3 = fmaf(R2C, vw, -d26w);
    oA[0] = CR0;        oB[0] = CR0;
    oA[4] = CR4;        oB[4] = CR4;
    oA[1] = CR1 - SW1;  oB[1] = CR1 + SW1;
    oA[2] = CR2 - SW2;  oB[2] = CR2 + SW2;
    oA[3] = CR3 - SW3;  oB[3] = CR3 + SW3;
    oA[5] = CR3 + SW3;  oB[5] = CR3 - SW3;
    oA[6] = CR2 + SW2;  oB[6] = CR2 - SW2;
    oA[7] = CR1 + SW1;  oB[7] = CR1 - SW1;
}

// Inverse combine for row pair (C0, C0+1). bb = 8 compressed columns,
// column k at bb[k*8 .. k*8+7] = {RE0..RE4, SI1..SI3}.
template<int C0>
__device__ __forceinline__ void combine_pair(const float* __restrict__ bb,
                                             float* oA, float* oB) {
    constexpr int JP[8]  = {0, 1, 2, 3, 4, 3, 2, 1};
    constexpr int IXt[8] = {0, 5, 6, 7, 0, 7, 6, 5};
    constexpr float SGt[8] = {0.f, 1.f, 1.f, 1.f, 0.f, -1.f, -1.f, -1.f};

    float q[8];
    #pragma unroll
    for (int k = 0; k < 8; k++) q[k] = bb[k * 8 + JP[C0]];
    if constexpr (SGt[C0] == 0.f) {
        dft8_cos(q, oA);
    } else {
        float w[8];
        #pragma unroll
        for (int k = 0; k < 8; k++) w[k] = SGt[C0] * bb[k * 8 + IXt[C0]];
        dft8_combine(q, w, oA);
    }
    float q2[8], w2[8];
    #pragma unroll
    for (int k = 0; k < 8; k++) {
        q2[k] = bb[k * 8 + JP[C0 + 1]];
        w2[k] = SGt[C0 + 1] * bb[k * 8 + IXt[C0 + 1]];
    }
    dft8_combine(q2, w2, oB);
}

// Haar refine for a row pair (fully thread-local).
__device__ __forceinline__ void haar_pair(const float* e, const float* o,
                                          float* re, float* ro) {
    #pragma unroll
    for (int m = 0; m < 4; m++) {
        float a = e[2*m], b = e[2*m+1], c = o[2*m], d = o[2*m+1];
        float u0 = a + b, v0 = a - b, u1 = c + d, v1 = c - d;
        float LL = (u0 + u1) * 0.5f;
        float LH = soft05((u0 - u1) * 0.5f);
        float HL = soft05((v0 + v1) * 0.5f);
        float HH = soft05((v0 - v1) * 0.5f);
        float p  = LL + LH, qd = HL + HH;
        float rr = LL - LH, sd = HL - HH;
        re[2*m]   = 0.5f * (p + qd);
        re[2*m+1] = 0.5f * (p - qd);
        ro[2*m]   = 0.5f * (rr + sd);
        ro[2*m+1] = 0.5f * (rr - sd);
    }
}

__device__ __forceinline__ void nonlin8(float* c) {
    #pragma unroll
    for (int i = 0; i < 8; i++) {
        float v = c[i] * 0.125f;                 // fold ortho 1/8
        float m = fminf(fabsf(v) * 0.4f, 1.0f);  // shrink below 2.5
        v *= m;
        c[i] = fminf(fmaxf(v, -10.0f), 10.0f);   // clip
    }
}

#define BSTR 65     // odd block stride -> scalar bufF LDS/STS conflict-free
#define PF4 129     // g-panel stride in float4 (odd -> conflict-free)

// CTA = 64x64 px, 256 threads, TARGET 7 CTAs/SM (smem 33.2KB, regs <= 36).
// Loader: thread = (p,h,chain) computes full 2D blur for 4-row x 4-col patch.
// Transform: blk = t&63 (bcol=blk&7, brow=blk>>3), r2 = t>>6 (warp-uniform)
// -> owns block rows 2r2, 2r2+1; forward column stage owns conjugate columns
// {r2, 8-r2} ({0,4} for r2=0).
__global__ __launch_bounds__(256, 7) void sas_fusedA_kernel(
    const float* __restrict__ in, float* __restrict__ out)
{
    __shared__ __align__(16) float4 gpan[8 * PF4];   // blurred g panels
    __shared__ __align__(16) float bufF[64 * BSTR];  // transpose buffer (x2)

    const int t = threadIdx.x;
    const int tileX = blockIdx.x * 64;
    const int tileY = blockIdx.y * 64;
    const int z = blockIdx.z;
    const float* img = in + (size_t)z * (512 * 512);

    const float e1 = expf(-0.78125f);            // exp(-1/(2*0.8^2))
    const float w0 = 1.0f / (1.0f + 2.0f * e1);
    const float w1 = e1 * w0;

    // ---- Loader: FULL 2D blur, global -> g panels ----
    {
        const int l16 = t & 15;
        const int p  = l16 & 7;                  // panel (bcol)
        const int hh = l16 >> 3;                 // half of panel row
        const int cc = 2 * p + hh;               // f4 column 0..15
        const int j  = t >> 4;                   // row chain 0..15
        const int base = tileX + 4 * cc;
        const int lanebase = t & 16;
        const int llane = lanebase + (hh ? p : (p + 7));
        const int rlane = lanebase + (hh ? (p + 1) : (p + 8));

        float4 h[6];
        #pragma unroll
        for (int r6 = 0; r6 < 6; r6++) {
            int gy = tileY + 4 * j - 1 + r6;
            gy = (gy < 0) ? -gy : ((gy > 511) ? 1022 - gy : gy);
            const float* rp = img + (size_t)gy * 512;
            float4 A = *(const float4*)(rp + base);
            float lv = __shfl_sync(0xffffffffu, A.w, llane);
            float rv = __shfl_sync(0xffffffffu, A.x, rlane);
            if (l16 == 0)  lv = (base == 0)   ? A.y : rp[base - 1];
            if (l16 == 15) rv = (base == 508) ? A.z : rp[base + 4];
            h[r6].x = fmaf(w1, lv  + A.y, w0 * A.x);
            h[r6].y = fmaf(w1, A.x + A.z, w0 * A.y);
            h[r6].z = fmaf(w1, A.y + A.w, w0 * A.z);
            h[r6].w = fmaf(w1, A.z + rv,  w0 * A.w);
        }
        #pragma unroll
        for (int k = 0; k < 4; k++) {
            float4 g;
            g.x = fmaf(w1, h[k].x + h[k + 2].x, w0 * h[k + 1].x);
            g.y = fmaf(w1, h[k].y + h[k + 2].y, w0 * h[k + 1].y);
            g.z = fmaf(w1, h[k].z + h[k + 2].z, w0 * h[k + 1].z);
            g.w = fmaf(w1, h[k].w + h[k + 2].w, w0 * h[k + 1].w);
            gpan[PF4 * p + 2 * (4 * j + k) + hh] = g;
        }
    }
    __syncthreads();

    const int r2 = t >> 6;
    const int blk = t & 63;
    const int bcol = blk & 7;
    const int brow = blk >> 3;
    const int R0 = brow * 8 + 2 * r2;            // strip-local row
    const float4* gp = gpan + PF4 * bcol + 2 * R0;   // rows R0, R0+1
    float* fb = bufF + blk * BSTR;

    // ---- Row DFT of g rows -> bufF (g NOT kept live) ----
    {
        float4 a = gp[0], b = gp[1], c = gp[2], d = gp[3];
        float g0[8] = {a.x, a.y, a.z, a.w, b.x, b.y, b.z, b.w};
        float g1[8] = {c.x, c.y, c.z, c.w, d.x, d.y, d.z, d.w};
        float ta[8], tb[8];
        dft8_real(g0, ta);
        dft8_real(g1, tb);
        #pragma unroll
        for (int s = 0; s < 8; s++) fb[(2 * r2) * 8 + s] = ta[s];
        #pragma unroll
        for (int s = 0; s < 8; s++) fb[(2 * r2 + 1) * 8 + s] = tb[s];
    }
    __syncthreads();

    // ---- Forward column stage: conjugate pair {tau, 8-tau} in one pass ----
    float sA[8], sB[8];
    int c2;                                      // second column index
    {
        float q[8], w[8];
        #pragma unroll
        for (int k = 0; k < 8; k++) {
            q[k] = fb[k * 8 + r2];               // slot tau   (RE_tau)
            w[k] = fb[k * 8 + 4 + r2];           // slot tau+4 (SI_tau / RE4)
        }
        float cA[8], cB[8];
        if (r2 == 0) {                           // cols 0 and 4: cos-only
            dft8_cos(q, cA);
            dft8_cos(w, cB);                     // w holds slot 4 = RE4
            c2 = 4;
        } else {                                 // cols tau and 8-tau
            dft8_dual(q, w, cA, cB);
            c2 = 8 - r2;
        }
        nonlin8(cA);
        nonlin8(cB);
        dft8_real(cA, sA);
        dft8_real(cB, sB);
    }
    __syncthreads();                             // all bufF reads complete
    #pragma unroll
    for (int s = 0; s < 8; s++) fb[r2 * 8 + s] = sA[s];
    {
        float* fb2 = bufF + blk * BSTR + c2 * 8;
        #pragma unroll
        for (int s = 0; s < 8; s++) fb2[s] = sB[s];
    }
    __syncthreads();

    // ---- Inverse row combine (rows 2r2, 2r2+1) ----
    float idA[8], idB[8];
    switch (r2) {
        case 0: combine_pair<0>(fb, idA, idB); break;
        case 1: combine_pair<2>(fb, idA, idB); break;
        case 2: combine_pair<4>(fb, idA, idB); break;
        default: combine_pair<6>(fb, idA, idB); break;
    }
    #pragma unroll
    for (int x = 0; x < 8; x++) { idA[x] *= 0.125f; idB[x] *= 0.125f; }

    const int bidx = z / 3;
    const int cch = z - bidx * 3;
    const size_t obase =
        ((size_t)(bidx * 6 + cch) * 512 + (tileY + R0)) * 512 + tileX + bcol * 8;

    // ---- I-branch: haar + store ----
    {
        float oa[8], ob[8];
        haar_pair(idA, idB, oa, ob);
        float4* p0 = (float4*)(out + obase);
        p0[0] = make_float4(oa[0], oa[1], oa[2], oa[3]);
        p0[1] = make_float4(oa[4], oa[5], oa[6], oa[7]);
        float4* p1 = (float4*)(out + obase + 512);
        p1[0] = make_float4(ob[0], ob[1], ob[2], ob[3]);
        p1[1] = make_float4(ob[4], ob[5], ob[6], ob[7]);
    }

    // ---- R-branch: reload g from panels, residual, haar, store ----
    {
        float4 a = gp[0], b = gp[1], c = gp[2], d = gp[3];
        float rdA[8] = {a.x - idA[0], a.y - idA[1], a.z - idA[2], a.w - idA[3],
                        b.x - idA[4], b.y - idA[5], b.z - idA[6], b.w - idA[7]};
        float rdB[8] = {c.x - idB[0], c.y - idB[1], c.z - idB[2], c.w - idB[3],
                        d.x - idB[4], d.y - idB[5], d.z - idB[6], d.w - idB[7]};
        float oa[8], ob[8];
        haar_pair(rdA, rdB, oa, ob);
        const size_t rbase = obase + (size_t)3 * 512 * 512;
        float4* p0 = (float4*)(out + rbase);
        p0[0] = make_float4(oa[0], oa[1], oa[2], oa[3]);
        p0[1] = make_float4(oa[4], oa[5], oa[6], oa[7]);
        float4* p1 = (float4*)(out + rbase + 512);
        p1[0] = make_float4(ob[0], ob[1], ob[2], ob[3]);
        p1[1] = make_float4(ob[4], ob[5], ob[6], ob[7]);
    }
}

extern "C" void kernel_launch(void* const* d_in, const int* in_sizes, int n_in,
                              void* d_out, int out_size) {
    const float* I = (const float*)d_in[0];
    float* out = (float*)d_out;
    dim3 block(256);
    dim3 grid(8, 8, 96);
    sas_fusedA_kernel<<<grid, block>>>(I, out);
}

// round 13
// speedup vs baseline: 1.1884x; 1.1884x over previous
#include <cuda_runtime.h>
#include <cuda_bf16.h>

#define R2C 0.70710678118654752f

__device__ __forceinline__ float soft05(float x) {
    return copysignf(fmaxf(fabsf(x) - 0.05f, 0.0f), x);
}

// x[8] -> o[8] = {RE0,RE1,RE2,RE3,RE4,SI1,SI2,SI3}, unnormalized.
__device__ __forceinline__ void dft8_real(const float* x, float* o) {
    float s04 = x[0] + x[4], d04 = x[0] - x[4];
    float s26 = x[2] + x[6], d26 = x[2] - x[6];
    float s15 = x[1] + x[5], d15 = x[1] - x[5];
    float s37 = x[3] + x[7], d37 = x[3] - x[7];
    float t1 = s04 + s26, t2 = s15 + s37;
    o[0] = t1 + t2; o[4] = t1 - t2; o[2] = s04 - s26;
    float u = d15 - d37, v = d15 + d37;
    o[1] = fmaf(R2C, u, d04); o[3] = fmaf(-R2C, u, d04);
    o[5] = fmaf(R2C, v, d26);
    o[6] = s15 - s37;
    o[7] = fmaf(R2C, v, -d26);
}

// o[u] = cosDFT_u(q) - sinDFT_u(w), raw/unscaled.
__device__ __forceinline__ void dft8_combine(const float* q, const float* w, float* o) {
    float s04 = q[0] + q[4], d04 = q[0] - q[4];
    float s26 = q[2] + q[6];
    float s15 = q[1] + q[5], d15 = q[1] - q[5];
    float s37 = q[3] + q[7], d37 = q[3] - q[7];
    float t1 = s04 + s26, t2 = s15 + s37;
    float RE0 = t1 + t2, RE4 = t1 - t2, RE2 = s04 - s26;
    float uq = d15 - d37;
    float RE1 = fmaf(R2C, uq, d04), RE3 = fmaf(-R2C, uq, d04);
    float d26w = w[2] - w[6];
    float vw = (w[1] - w[5]) + (w[3] - w[7]);
    float SI1 = fmaf(R2C, vw, d26w);
    float SI2 = (w[1] + w[5]) - (w[3] + w[7]);
    float SI3 = fmaf(R2C, vw, -d26w);
    o[0] = RE0;        o[4] = RE4;
    o[1] = RE1 - SI1;  o[7] = RE1 + SI1;
    o[2] = RE2 - SI2;  o[6] = RE2 + SI2;
    o[3] = RE3 - SI3;  o[5] = RE3 + SI3;
}

// o[u] = cosDFT_u(q) only (for lines with zero sine part).
__device__ __forceinline__ void dft8_cos(const float* q, float* o) {
    float s04 = q[0] + q[4], d04 = q[0] - q[4];
    float s26 = q[2] + q[6];
    float s15 = q[1] + q[5], d15 = q[1] - q[5];
    float s37 = q[3] + q[7], d37 = q[3] - q[7];
    float t1 = s04 + s26, t2 = s15 + s37;
    o[0] = t1 + t2; o[4] = t1 - t2;
    o[2] = s04 - s26; o[6] = o[2];
    float uq = d15 - d37;
    o[1] = fmaf(R2C, uq, d04); o[3] = fmaf(-R2C, uq, d04);
    o[5] = o[3]; o[7] = o[1];
}

// Dual conjugate columns: CR = cosDFT(q), SW = sinDFT(w).
// oA[u] = CR[u] - SW[u] (col tau), oB[u] = CR[u] + SW[u] (col 8-tau).
__device__ __forceinline__ void dft8_dual(const float* q, const float* w,
                                          float* oA, float* oB) {
    float s04 = q[0] + q[4], d04 = q[0] - q[4];
    float s26 = q[2] + q[6];
    float s15 = q[1] + q[5], d15 = q[1] - q[5];
    float s37 = q[3] + q[7], d37 = q[3] - q[7];
    float t1 = s04 + s26, t2 = s15 + s37;
    float CR0 = t1 + t2, CR4 = t1 - t2, CR2 = s04 - s26;
    float uq = d15 - d37;
    float CR1 = fmaf(R2C, uq, d04), CR3 = fmaf(-R2C, uq, d04);
    float d26w = w[2] - w[6];
    float vw = (w[1] - w[5]) + (w[3] - w[7]);
    float SW1 = fmaf(R2C, vw, d26w);
    float SW2 = (w[1] + w[5]) - (w[3] + w[7]);
    float SW3 = fmaf(R2C, vw, -d26w);
    oA[0] = CR0;        oB[0] = CR0;
    oA[4] = CR4;        oB[4] = CR4;
    oA[1] = CR1 - SW1;  oB[1] = CR1 + SW1;
    oA[2] = CR2 - SW2;  oB[2] = CR2 + SW2;
    oA[3] = CR3 - SW3;  oB[3] = CR3 + SW3;
    oA[5] = CR3 + SW3;  oB[5] = CR3 - SW3;
    oA[6] = CR2 + SW2;  oB[6] = CR2 - SW2;
    oA[7] = CR1 + SW1;  oB[7] = CR1 - SW1;
}

// Inverse combine for row pair (C0, C0+1). bb = 8 compressed columns,
// column k at bb[k*8 .. k*8+7] = {RE0..RE4, SI1..SI3}.
template<int C0>
__device__ __forceinline__ void combine_pair(const float* __restrict__ bb,
                                             float* oA, float* oB) {
    constexpr int JP[8]  = {0, 1, 2, 3, 4, 3, 2, 1};
    constexpr int IXt[8] = {0, 5, 6, 7, 0, 7, 6, 5};
    constexpr float SGt[8] = {0.f, 1.f, 1.f, 1.f, 0.f, -1.f, -1.f, -1.f};

    float q[8];
    #pragma unroll
    for (int k = 0; k < 8; k++) q[k] = bb[k * 8 + JP[C0]];
    if constexpr (SGt[C0] == 0.f) {
        dft8_cos(q, oA);
    } else {
        float w[8];
        #pragma unroll
        for (int k = 0; k < 8; k++) w[k] = SGt[C0] * bb[k * 8 + IXt[C0]];
        dft8_combine(q, w, oA);
    }
    float q2[8], w2[8];
    #pragma unroll
    for (int k = 0; k < 8; k++) {
        q2[k] = bb[k * 8 + JP[C0 + 1]];
        w2[k] = SGt[C0 + 1] * bb[k * 8 + IXt[C0 + 1]];
    }
    dft8_combine(q2, w2, oB);
}

// Haar refine for a row pair (fully thread-local).
__device__ __forceinline__ void haar_pair(const float* e, const float* o,
                                          float* re, float* ro) {
    #pragma unroll
    for (int m = 0; m < 4; m++) {
        float a = e[2*m], b = e[2*m+1], c = o[2*m], d = o[2*m+1];
        float u0 = a + b, v0 = a - b, u1 = c + d, v1 = c - d;
        float LL = (u0 + u1) * 0.5f;
        float LH = soft05((u0 - u1) * 0.5f);
        float HL = soft05((v0 + v1) * 0.5f);
        float HH = soft05((v0 - v1) * 0.5f);
        float p  = LL + LH, qd = HL + HH;
        float rr = LL - LH, sd = HL - HH;
        re[2*m]   = 0.5f * (p + qd);
        re[2*m+1] = 0.5f * (p - qd);
        ro[2*m]   = 0.5f * (rr + sd);
        ro[2*m+1] = 0.5f * (rr - sd);
    }
}

__device__ __forceinline__ void nonlin8(float* c) {
    #pragma unroll
    for (int i = 0; i < 8; i++) {
        float v = c[i] * 0.125f;                 // fold ortho 1/8
        float m = fminf(fabsf(v) * 0.4f, 1.0f);  // shrink below 2.5
        v *= m;
        c[i] = fminf(fmaxf(v, -10.0f), 10.0f);   // clip
    }
}

// Vertical 3-tap blur for two consecutive rows, half-split to bound liveness.
__device__ __forceinline__ void vblur2(const float4* __restrict__ hp,
                                       float w0, float w1,
                                       float* g0, float* g1) {
    #pragma unroll
    for (int h = 0; h < 2; h++) {
        float4 A = hp[h], B = hp[2 + h], C = hp[4 + h], D = hp[6 + h];
        g0[4*h+0] = fmaf(w1, A.x + C.x, w0 * B.x);
        g0[4*h+1] = fmaf(w1, A.y + C.y, w0 * B.y);
        g0[4*h+2] = fmaf(w1, A.z + C.z, w0 * B.z);
        g0[4*h+3] = fmaf(w1, A.w + C.w, w0 * B.w);
        g1[4*h+0] = fmaf(w1, B.x + D.x, w0 * C.x);
        g1[4*h+1] = fmaf(w1, B.y + D.y, w0 * C.y);
        g1[4*h+2] = fmaf(w1, B.z + D.z, w0 * C.z);
        g1[4*h+3] = fmaf(w1, B.w + D.w, w0 * C.w);
    }
}

#define BSTR 65    // odd block stride -> scalar bufF LDS/STS conflict-free
#define PSTR 276   // panel stride floats (34 rows x 8 + pad; 276 % 8 == 4)

// CTA = 64x32 px, 128 threads (12 CTAs/SM target, occ 75%).
// Thread: blk = t&31 (bcol=blk&7, brow=blk>>3), r2 = t>>5 (warp-uniform)
// -> owns block rows 2r2, 2r2+1; forward column stage owns conjugate
// columns {r2, 8-r2} ({0,4} for r2=0).
__global__ __launch_bounds__(128, 12) void sas_fusedB_kernel(
    const float* __restrict__ in, float* __restrict__ out)
{
    __shared__ __align__(16) float smemA[8 * PSTR];  // hblur panels, persist
    __shared__ __align__(16) float bufF[32 * BSTR];  // transpose buffer (x2)

    const int t = threadIdx.x;
    const int tileX = blockIdx.x * 64;
    const int tileY = blockIdx.y * 32;
    const int z = blockIdx.z;
    const float* img = in + (size_t)z * (512 * 512);

    const float e1 = expf(-0.78125f);            // exp(-1/(2*0.8^2))
    const float w0 = 1.0f / (1.0f + 2.0f * e1);
    const float w1 = e1 * w0;

    // ---- Loader: horizontal blur, global -> smem panels (34 rows) ----
    for (int s = t; s < 544; s += 128) {         // 34 rows x 16 f4
        int row = s >> 4, f4c = s & 15;
        int gy = tileY + row - 1;
        gy = (gy < 0) ? -gy : ((gy > 511) ? 1022 - gy : gy);
        const float* rp = img + (size_t)gy * 512;
        int base = tileX + f4c * 4;
        float4 A = *(const float4*)(rp + base);
        float lv = __shfl_up_sync(0xffffffffu, A.w, 1);
        float rv = __shfl_down_sync(0xffffffffu, A.x, 1);
        if (f4c == 0)  lv = (base == 0)   ? A.y : rp[base - 1];
        if (f4c == 15) rv = (base == 508) ? A.z : rp[base + 4];
        float4 o;
        o.x = fmaf(w1, lv  + A.y, w0 * A.x);
        o.y = fmaf(w1, A.x + A.z, w0 * A.y);
        o.z = fmaf(w1, A.y + A.w, w0 * A.z);
        o.w = fmaf(w1, A.z + rv,  w0 * A.w);
        *(float4*)(smemA + (f4c >> 1) * PSTR + row * 8 + (f4c & 1) * 4) = o;
    }
    __syncthreads();

    const int r2 = t >> 5;                       // warp-uniform
    const int blk = t & 31;
    const int bcol = blk & 7;
    const int brow = blk >> 3;
    const int R0 = brow * 8 + 2 * r2;            // strip-local row 0..30
    const float4* hp = (const float4*)(smemA + bcol * PSTR + R0 * 8);
    float* fb = bufF + blk * BSTR;

    // ---- Vertical blur (2 rows) + row DFT -> bufF (g NOT kept live) ----
    {
        float g0[8], g1[8];
        vblur2(hp, w0, w1, g0, g1);
        float ta[8], tb[8];
        dft8_real(g0, ta);
        dft8_real(g1, tb);
        #pragma unroll
        for (int s = 0; s < 8; s++) fb[(2 * r2) * 8 + s] = ta[s];
        #pragma unroll
        for (int s = 0; s < 8; s++) fb[(2 * r2 + 1) * 8 + s] = tb[s];
    }
    __syncthreads();

    // ---- Forward column stage: conjugate pair {tau, 8-tau} in one pass ----
    float sA[8], sB[8];
    int c2;                                      // second column index
    {
        float q[8], w[8];
        #pragma unroll
        for (int k = 0; k < 8; k++) {
            q[k] = fb[k * 8 + r2];               // slot tau   (RE_tau)
            w[k] = fb[k * 8 + 4 + r2];           // slot tau+4 (SI_tau / RE4)
        }
        float cA[8], cB[8];
        if (r2 == 0) {                           // cols 0 and 4: cos-only
            dft8_cos(q, cA);
            dft8_cos(w, cB);                     // w holds slot 4 = RE4
            c2 = 4;
        } else {                                 // cols tau and 8-tau
            dft8_dual(q, w, cA, cB);
            c2 = 8 - r2;
        }
        nonlin8(cA);
        nonlin8(cB);
        dft8_real(cA, sA);
        dft8_real(cB, sB);
    }
    __syncthreads();                             // all bufF reads complete
    #pragma unroll
    for (int s = 0; s < 8; s++) fb[r2 * 8 + s] = sA[s];
    {
        float* fb2 = bufF + blk * BSTR + c2 * 8;
        #pragma unroll
        for (int s = 0; s < 8; s++) fb2[s] = sB[s];
    }
    __syncthreads();

    // ---- Inverse row combine (rows 2r2, 2r2+1) ----
    float idA[8], idB[8];
    switch (r2) {
        case 0: combine_pair<0>(fb, idA, idB); break;
        case 1: combine_pair<2>(fb, idA, idB); break;
        case 2: combine_pair<4>(fb, idA, idB); break;
        default: combine_pair<6>(fb, idA, idB); break;
    }
    #pragma unroll
    for (int x = 0; x < 8; x++) { idA[x] *= 0.125f; idB[x] *= 0.125f; }

    const int bidx = z / 3;
    const int cch = z - bidx * 3;
    const size_t obase =
        ((size_t)(bidx * 6 + cch) * 512 + (tileY + R0)) * 512 + tileX + bcol * 8;

    // ---- I-branch: haar + store ----
    {
        float oa[8], ob[8];
        haar_pair(idA, idB, oa, ob);
        float4* p0 = (float4*)(out + obase);
        p0[0] = make_float4(oa[0], oa[1], oa[2], oa[3]);
        p0[1] = make_float4(oa[4], oa[5], oa[6], oa[7]);
        float4* p1 = (float4*)(out + obase + 512);
        p1[0] = make_float4(ob[0], ob[1], ob[2], ob[3]);
        p1[1] = make_float4(ob[4], ob[5], ob[6], ob[7]);
    }

    // ---- R-branch: recompute blur from persistent smemA, residual, haar ----
    {
        float rdA[8], rdB[8];
        vblur2(hp, w0, w1, rdA, rdB);            // rd = g (then subtract id)
        #pragma unroll
        for (int x = 0; x < 8; x++) { rdA[x] -= idA[x]; rdB[x] -= idB[x]; }
        float oa[8], ob[8];
        haar_pair(rdA, rdB, oa, ob);
        const size_t rbase = obase + (size_t)3 * 512 * 512;
        float4* p0 = (float4*)(out + rbase);
        p0[0] = make_float4(oa[0], oa[1], oa[2], oa[3]);
        p0[1] = make_float4(oa[4], oa[5], oa[6], oa[7]);
        float4* p1 = (float4*)(out + rbase + 512);
        p1[0] = make_float4(ob[0], ob[1], ob[2], ob[3]);
        p1[1] = make_float4(ob[4], ob[5], ob[6], ob[7]);
    }
}

extern "C" void kernel_launch(void* const* d_in, const int* in_sizes, int n_in,
                              void* d_out, int out_size) {
    const float* I = (const float*)d_in[0];
    float* out = (float*)d_out;
    dim3 block(128);
    dim3 grid(8, 16, 96);
    sas_fusedB_kernel<<<grid, block>>>(I, out);
}